// round 2
// baseline (speedup 1.0000x reference)
#include <cuda_runtime.h>
#include <math.h>

// ---------------- problem constants ----------------
#define TT   2048
#define HID  3584
#define NH   16
#define NKV  8
#define HD   256
#define QKV_N ((NH + 2 * NKV) * HD)   // 8192
#define OPROJ_K (NH * HD)             // 4096

__device__ __align__(16) float g_qkv[(size_t)TT * QKV_N];    // 64 MB scratch
__device__ __align__(16) float g_attn[(size_t)TT * OPROJ_K]; // 32 MB scratch

// ---------------- SGEMM: C[M,N] = A[M,K] @ B[K,N], all row-major, fp32 ----------------
// BM=BN=128, BK=16, 256 threads, 8x8 per-thread micro tile, register-prefetch pipelined.
__global__ __launch_bounds__(256, 2) void sgemm_kernel(const float* __restrict__ A,
                                                       const float* __restrict__ B,
                                                       float* __restrict__ C,
                                                       int M, int N, int K) {
    __shared__ float As[16][128];  // transposed A tile: As[k][m]
    __shared__ float Bs[16][128];  // Bs[k][n]

    const int tid = threadIdx.x;
    const int tr  = tid >> 4;       // 0..15
    const int tc  = tid & 15;       // 0..15
    const int rowBase = blockIdx.y * 128;
    const int colBase = blockIdx.x * 128;

    const int aRow  = tid >> 2;          // 0..63 (+64)
    const int aCol  = (tid & 3) << 2;    // 0,4,8,12
    const int bRow  = tid >> 5;          // 0..7 (+8)
    const int bCol  = (tid & 31) << 2;   // 0..124

    const float* Aptr = A + (size_t)rowBase * K;
    const float* Bptr = B + colBase;

    float acc[8][8];
#pragma unroll
    for (int i = 0; i < 8; ++i)
#pragma unroll
        for (int j = 0; j < 8; ++j) acc[i][j] = 0.f;

    float4 pa[2], pb[2];
    // prefetch tile 0 into registers
#pragma unroll
    for (int h = 0; h < 2; ++h)
        pa[h] = *reinterpret_cast<const float4*>(Aptr + (size_t)(aRow + h * 64) * K + aCol);
#pragma unroll
    for (int h = 0; h < 2; ++h)
        pb[h] = *reinterpret_cast<const float4*>(Bptr + (size_t)(bRow + h * 8) * N + bCol);

    for (int k0 = 0; k0 < K; k0 += 16) {
        // commit prefetched registers to smem
#pragma unroll
        for (int h = 0; h < 2; ++h) {
            int r = aRow + h * 64;
            As[aCol + 0][r] = pa[h].x;
            As[aCol + 1][r] = pa[h].y;
            As[aCol + 2][r] = pa[h].z;
            As[aCol + 3][r] = pa[h].w;
        }
#pragma unroll
        for (int h = 0; h < 2; ++h)
            *reinterpret_cast<float4*>(&Bs[bRow + h * 8][bCol]) = pb[h];
        __syncthreads();

        // prefetch next tile while computing this one
        const int kn = k0 + 16;
        if (kn < K) {
#pragma unroll
            for (int h = 0; h < 2; ++h)
                pa[h] = *reinterpret_cast<const float4*>(Aptr + (size_t)(aRow + h * 64) * K + kn + aCol);
#pragma unroll
            for (int h = 0; h < 2; ++h)
                pb[h] = *reinterpret_cast<const float4*>(Bptr + (size_t)(kn + bRow + h * 8) * N + bCol);
        }

#pragma unroll
        for (int kk = 0; kk < 16; ++kk) {
            float a[8], b[8];
            float4 a0 = *reinterpret_cast<const float4*>(&As[kk][tr * 8]);
            float4 a1 = *reinterpret_cast<const float4*>(&As[kk][tr * 8 + 4]);
            float4 b0 = *reinterpret_cast<const float4*>(&Bs[kk][tc * 8]);
            float4 b1 = *reinterpret_cast<const float4*>(&Bs[kk][tc * 8 + 4]);
            a[0]=a0.x; a[1]=a0.y; a[2]=a0.z; a[3]=a0.w;
            a[4]=a1.x; a[5]=a1.y; a[6]=a1.z; a[7]=a1.w;
            b[0]=b0.x; b[1]=b0.y; b[2]=b0.z; b[3]=b0.w;
            b[4]=b1.x; b[5]=b1.y; b[6]=b1.z; b[7]=b1.w;
#pragma unroll
            for (int i = 0; i < 8; ++i)
#pragma unroll
                for (int j = 0; j < 8; ++j) acc[i][j] += a[i] * b[j];
        }
        __syncthreads();
    }

#pragma unroll
    for (int i = 0; i < 8; ++i) {
        int r = rowBase + tr * 8 + i;
#pragma unroll
        for (int j = 0; j < 8; j += 4) {
            float4 v = make_float4(acc[i][j], acc[i][j + 1], acc[i][j + 2], acc[i][j + 3]);
            *reinterpret_cast<float4*>(C + (size_t)r * N + colBase + tc * 8 + j) = v;
        }
    }
}

// ---------------- RoPE (neox style, in place on q and k of g_qkv) ----------------
__global__ void rope_kernel(const int* __restrict__ positions) {
    int idx = blockIdx.x * blockDim.x + threadIdx.x;
    const int total = TT * (NH + NKV) * (HD / 2);
    if (idx >= total) return;
    int d    = idx & (HD / 2 - 1);          // 0..127
    int tmp  = idx >> 7;
    int head = tmp % (NH + NKV);            // 0..23 (q heads then k heads, contiguous)
    int t    = tmp / (NH + NKV);

    float pos = (float)positions[t];
    float inv = powf(10000.0f, -(float)d / 128.0f);
    float f   = pos * inv;
    float c   = cosf(f), s = sinf(f);

    float* base = g_qkv + (size_t)t * QKV_N + head * HD;
    float x1 = base[d];
    float x2 = base[d + HD / 2];
    base[d]          = x1 * c - x2 * s;
    base[d + HD / 2] = x2 * c + x1 * s;
}

// ---------------- Flash attention fp32, BQ=BK=64, HD=256 ----------------
// grid: (T/64, NH), block: 256 threads.
#define QK_STRIDE 257
#define SS_STRIDE 65
#define ATTN_SMEM_FLOATS (3 * 64 * QK_STRIDE + 64 * SS_STRIDE + 3 * 64)
#define ATTN_SMEM_BYTES  (ATTN_SMEM_FLOATS * 4)

__global__ __launch_bounds__(256) void attn_kernel() {
    extern __shared__ float sm[];
    float* Qs  = sm;
    float* Ks  = Qs + 64 * QK_STRIDE;
    float* Vs  = Ks + 64 * QK_STRIDE;
    float* Ss  = Vs + 64 * QK_STRIDE;
    float* m_s = Ss + 64 * SS_STRIDE;
    float* l_s = m_s + 64;
    float* a_s = l_s + 64;

    const int tid = threadIdx.x;
    const int qt  = gridDim.x - 1 - blockIdx.x;   // heavy (large-qt) tiles launch first
    const int h   = blockIdx.y;
    const int kh  = h >> 1;                  // GQA: 2 q heads per kv head
    const int tr  = tid >> 4;                // 0..15
    const int tc  = tid & 15;                // 0..15

    const float SCALE = 0.0625f;             // 256^-0.5
    const float CAP   = 50.0f;

    // load Q tile (64 x 256)
    {
        const float* qg = g_qkv + (size_t)(qt * 64) * QKV_N + h * HD;
        for (int i = tid; i < 64 * 64; i += 256) {
            int r  = i >> 6;
            int c4 = (i & 63) << 2;
            float4 v = *reinterpret_cast<const float4*>(qg + (size_t)r * QKV_N + c4);
            float* dst = &Qs[r * QK_STRIDE + c4];
            dst[0] = v.x; dst[1] = v.y; dst[2] = v.z; dst[3] = v.w;
        }
    }
    if (tid < 64) { m_s[tid] = -1e30f; l_s[tid] = 0.f; }

    float acc[4][16];
#pragma unroll
    for (int i = 0; i < 4; ++i)
#pragma unroll
        for (int j = 0; j < 16; ++j) acc[i][j] = 0.f;

    for (int kt = 0; kt <= qt; ++kt) {
        __syncthreads();   // previous-iteration reads of Ks/Vs/Ss done; Q/m/l init visible
        {
            const float* kg = g_qkv + (size_t)(kt * 64) * QKV_N + NH * HD + kh * HD;
            const float* vg = g_qkv + (size_t)(kt * 64) * QKV_N + (NH + NKV) * HD + kh * HD;
            for (int i = tid; i < 64 * 64; i += 256) {
                int r  = i >> 6;
                int c4 = (i & 63) << 2;
                float4 kv = *reinterpret_cast<const float4*>(kg + (size_t)r * QKV_N + c4);
                float* kd = &Ks[r * QK_STRIDE + c4];
                kd[0] = kv.x; kd[1] = kv.y; kd[2] = kv.z; kd[3] = kv.w;
                float4 vv = *reinterpret_cast<const float4*>(vg + (size_t)r * QKV_N + c4);
                float* vd = &Vs[r * QK_STRIDE + c4];
                vd[0] = vv.x; vd[1] = vv.y; vd[2] = vv.z; vd[3] = vv.w;
            }
        }
        __syncthreads();

        // S = Q K^T  (4x4 per thread, interleaved rows/cols with stride 16)
        float s[4][4];
#pragma unroll
        for (int i = 0; i < 4; ++i)
#pragma unroll
            for (int j = 0; j < 4; ++j) s[i][j] = 0.f;

#pragma unroll 4
        for (int d = 0; d < HD; ++d) {
            float qv[4], kv[4];
#pragma unroll
            for (int i = 0; i < 4; ++i) qv[i] = Qs[(tr + 16 * i) * QK_STRIDE + d];
#pragma unroll
            for (int j = 0; j < 4; ++j) kv[j] = Ks[(tc + 16 * j) * QK_STRIDE + d];
#pragma unroll
            for (int i = 0; i < 4; ++i)
#pragma unroll
                for (int j = 0; j < 4; ++j) s[i][j] += qv[i] * kv[j];
        }

        // scale + softcap + causal mask -> Ss
#pragma unroll
        for (int i = 0; i < 4; ++i) {
            int qrow = qt * 64 + tr + 16 * i;
#pragma unroll
            for (int j = 0; j < 4; ++j) {
                int kcol = kt * 64 + tc + 16 * j;
                float x = s[i][j] * SCALE;
                x = CAP * tanhf(x * (1.0f / CAP));
                if (kcol > qrow) x = -1e30f;
                Ss[(tr + 16 * i) * SS_STRIDE + (tc + 16 * j)] = x;
            }
        }
        __syncthreads();

        // online softmax bookkeeping: 4 threads per row, shfl reduce within quad
        {
            const int row = tid >> 2;        // 0..63
            const int q4  = tid & 3;         // 0..3
            float* srow = &Ss[row * SS_STRIDE + q4 * 16];

            float mold = m_s[row];
            float mt = mold;
#pragma unroll
            for (int c = 0; c < 16; ++c) mt = fmaxf(mt, srow[c]);
            mt = fmaxf(mt, __shfl_xor_sync(0xFFFFFFFFu, mt, 1));
            mt = fmaxf(mt, __shfl_xor_sync(0xFFFFFFFFu, mt, 2));

            float sum = 0.f;
#pragma unroll
            for (int c = 0; c < 16; ++c) {
                float p = __expf(srow[c] - mt);
                srow[c] = p;
                sum += p;
            }
            sum += __shfl_xor_sync(0xFFFFFFFFu, sum, 1);
            sum += __shfl_xor_sync(0xFFFFFFFFu, sum, 2);

            if (q4 == 0) {
                float alpha = __expf(mold - mt);
                l_s[row] = l_s[row] * alpha + sum;
                m_s[row] = mt;
                a_s[row] = alpha;
            }
        }
        __syncthreads();

        // rescale accumulators, then O += P @ V
        float al[4];
#pragma unroll
        for (int i = 0; i < 4; ++i) al[i] = a_s[tr + 16 * i];
#pragma unroll
        for (int i = 0; i < 4; ++i)
#pragma unroll
            for (int j = 0; j < 16; ++j) acc[i][j] *= al[i];

#pragma unroll 4
        for (int k = 0; k < 64; ++k) {
            float p[4];
#pragma unroll
            for (int i = 0; i < 4; ++i) p[i] = Ss[(tr + 16 * i) * SS_STRIDE + k];
            float vv[16];
#pragma unroll
            for (int j = 0; j < 16; ++j) vv[j] = Vs[k * QK_STRIDE + tc + 16 * j];
#pragma unroll
            for (int i = 0; i < 4; ++i)
#pragma unroll
                for (int j = 0; j < 16; ++j) acc[i][j] += p[i] * vv[j];
        }
    }

    // write O
    float invl[4];
#pragma unroll
    for (int i = 0; i < 4; ++i) invl[i] = 1.0f / l_s[tr + 16 * i];
#pragma unroll
    for (int i = 0; i < 4; ++i) {
        size_t row = (size_t)(qt * 64 + tr + 16 * i);
#pragma unroll
        for (int j = 0; j < 16; ++j)
            g_attn[row * OPROJ_K + h * HD + tc + 16 * j] = acc[i][j] * invl[i];
    }
}

// ---------------- launch ----------------
extern "C" void kernel_launch(void* const* d_in, const int* in_sizes, int n_in,
                              void* d_out, int out_size) {
    const int*   positions = (const int*)d_in[0];
    const float* hidden    = (const float*)d_in[1];
    const float* w_qkv     = (const float*)d_in[2];
    const float* w_o       = (const float*)d_in[3];
    float*       out       = (float*)d_out;

    float *qkv_ptr = nullptr, *attn_ptr = nullptr;
    cudaGetSymbolAddress((void**)&qkv_ptr, g_qkv);
    cudaGetSymbolAddress((void**)&attn_ptr, g_attn);

    // 1) QKV projection: [T,HID] @ [HID, QKV_N]
    sgemm_kernel<<<dim3(QKV_N / 128, TT / 128), 256>>>(hidden, w_qkv, qkv_ptr, TT, QKV_N, HID);

    // 2) RoPE on q and k heads (in place)
    {
        int total = TT * (NH + NKV) * (HD / 2);
        rope_kernel<<<(total + 255) / 256, 256>>>(positions);
    }

    // 3) causal GQA attention with soft-cap
    cudaFuncSetAttribute(attn_kernel, cudaFuncAttributeMaxDynamicSharedMemorySize, ATTN_SMEM_BYTES);
    attn_kernel<<<dim3(TT / 64, NH), 256, ATTN_SMEM_BYTES>>>();

    // 4) output projection: [T, OPROJ_K] @ [OPROJ_K, HID]
    sgemm_kernel<<<dim3(HID / 128, TT / 128), 256>>>(attn_ptr, w_o, out, TT, HID, OPROJ_K);
}

// round 8
// speedup vs baseline: 1.4508x; 1.4508x over previous
#include <cuda_runtime.h>
#include <cuda_bf16.h>
#include <math.h>
#include <stdint.h>

// ---------------- problem constants ----------------
#define TT   2048
#define HID  3584
#define NH   16
#define NKV  8
#define HD   256
#define QKV_N ((NH + 2 * NKV) * HD)   // 8192
#define OPROJ_K (NH * HD)             // 4096

#define K3Q (3 * HID)      // 10752
#define K3O (3 * OPROJ_K)  // 12288

__device__ __align__(16) float g_qkv[(size_t)TT * QKV_N];
__device__ __align__(16) float g_attn[(size_t)TT * OPROJ_K];
__device__ __align__(16) __nv_bfloat16 g_Aq[(size_t)TT * K3Q];
__device__ __align__(16) __nv_bfloat16 g_Bq[(size_t)QKV_N * K3Q];
__device__ __align__(16) __nv_bfloat16 g_Ao[(size_t)TT * K3O];
__device__ __align__(16) __nv_bfloat16 g_Bo[(size_t)HID * K3O];

__device__ __forceinline__ uint32_t smem_u32(const void* p) {
    uint32_t a;
    asm("{ .reg .u64 t; cvta.to.shared.u64 t, %1; cvt.u32.u64 %0, t; }" : "=r"(a) : "l"(p));
    return a;
}
__device__ __forceinline__ void cp_async16(uint32_t saddr, const void* gaddr) {
    asm volatile("cp.async.cg.shared.global [%0], [%1], 16;" :: "r"(saddr), "l"(gaddr));
}
__device__ __forceinline__ void cp_commit() {
    asm volatile("cp.async.commit_group;");
}
__device__ __forceinline__ void cp_wait1() {
    asm volatile("cp.async.wait_group 1;");
}

// ============================================================
// conversion kernels: fp32 -> bf16 hi/lo split panels
// ============================================================
__global__ void conv_a_kernel(const float* __restrict__ A, __nv_bfloat16* __restrict__ A3,
                              int M, int K, int K3) {
    int idx = blockIdx.x * blockDim.x + threadIdx.x;
    if (idx >= M * K) return;
    int m = idx / K, k = idx - m * K;
    float x = A[idx];
    __nv_bfloat16 hi = __float2bfloat16(x);
    __nv_bfloat16 lo = __float2bfloat16(x - __bfloat162float(hi));
    size_t base = (size_t)m * K3;
    A3[base + k]         = hi;
    A3[base + K + k]     = lo;
    A3[base + 2 * K + k] = hi;
}

// W is [K, N] row-major; B'[n, {k, K+k}] = hi, B'[n, 2K+k] = lo
__global__ __launch_bounds__(256) void conv_bt_kernel(const float* __restrict__ W,
                                                      __nv_bfloat16* __restrict__ Bt,
                                                      int K, int N, int K3) {
    __shared__ float t[32][33];
    int n0 = blockIdx.x * 32, k0 = blockIdx.y * 32;
    int tx = threadIdx.x, ty = threadIdx.y;  // block (32, 8)
#pragma unroll
    for (int i = 0; i < 4; ++i)
        t[ty + 8 * i][tx] = W[(size_t)(k0 + ty + 8 * i) * N + n0 + tx];
    __syncthreads();
#pragma unroll
    for (int i = 0; i < 4; ++i) {
        int n = n0 + ty + 8 * i;
        int k = k0 + tx;
        float x = t[tx][ty + 8 * i];
        __nv_bfloat16 hi = __float2bfloat16(x);
        __nv_bfloat16 lo = __float2bfloat16(x - __bfloat162float(hi));
        size_t base = (size_t)n * K3;
        Bt[base + k]         = hi;
        Bt[base + K + k]     = hi;
        Bt[base + 2 * K + k] = lo;
    }
}

// ============================================================
// HMMA bf16 GEMM: C[M,N] fp32 = A'[M,K3] @ B'[N,K3]^T
// BM=BN=128, BK=32, 256 threads (8 warps: 2 m x 4 n), mma.m16n8k16,
// smem rows padded to 80B (conflict-free ldmatrix), 2-stage cp.async.
// ============================================================
#define HB_BM 128
#define HB_BN 128
#define HB_BK 32
#define ROWB 80   // bytes per smem row (32 bf16 = 64B data + 16B pad)

__global__ __launch_bounds__(256) void gemm_mma_kernel(const __nv_bfloat16* __restrict__ Ap,
                                                       const __nv_bfloat16* __restrict__ Bp,
                                                       float* __restrict__ C,
                                                       int N, int K3) {
    __shared__ __align__(16) char As[2][128 * ROWB];
    __shared__ __align__(16) char Bs[2][128 * ROWB];

    const int tid  = threadIdx.x;
    const int lane = tid & 31;
    const int wid  = tid >> 5;
    const int wm   = wid & 1;   // 0..1  (64-row slab)
    const int wn   = wid >> 1;  // 0..3  (32-col slab)
    const int rowBase = blockIdx.y * HB_BM;
    const int colBase = blockIdx.x * HB_BN;

    const uint32_t aS[2] = {smem_u32(As[0]), smem_u32(As[1])};
    const uint32_t bS[2] = {smem_u32(Bs[0]), smem_u32(Bs[1])};

    const __nv_bfloat16* Ag = Ap + (size_t)rowBase * K3;
    const __nv_bfloat16* Bg = Bp + (size_t)colBase * K3;

    // fill: 512 16B-chunks per matrix per stage; chunk = r*4 + c (gmem-coalesced)
    auto fill = [&](int buf, int k0) {
#pragma unroll
        for (int u = 0; u < 2; ++u) {
            int ch = tid + u * 256;
            int r = ch >> 2, c = ch & 3;
            cp_async16(aS[buf] + r * ROWB + c * 16, Ag + (size_t)r * K3 + k0 + c * 8);
        }
#pragma unroll
        for (int u = 0; u < 2; ++u) {
            int ch = tid + u * 256;
            int r = ch >> 2, c = ch & 3;
            cp_async16(bS[buf] + r * ROWB + c * 16, Bg + (size_t)r * K3 + k0 + c * 8);
        }
        cp_commit();
    };

    float acc[4][4][4];
#pragma unroll
    for (int i = 0; i < 4; ++i)
#pragma unroll
        for (int j = 0; j < 4; ++j)
#pragma unroll
            for (int e = 0; e < 4; ++e) acc[i][j][e] = 0.f;

    const int NIT = K3 / HB_BK;
    fill(0, 0);
    fill(1, HB_BK);

    // precomputed ldmatrix lane addressing offsets
    const int aRowOff = (lane & 7) + ((lane >> 3) & 1) * 8;  // row within 16-tile
    const int aColOff = (lane >> 4) * 16;                    // 0 or 16 bytes
    const int lnb     = lane & 15;
    const int bRowOff = lnb & 7;
    const int bColOff = (lnb >> 3) * 16;

    for (int it = 0; it < NIT; ++it) {
        const int buf = it & 1;
        cp_wait1();
        __syncthreads();

#pragma unroll
        for (int ks = 0; ks < 2; ++ks) {
            uint32_t af[4][4];
#pragma unroll
            for (int i = 0; i < 4; ++i) {
                uint32_t addr = aS[buf] + (wm * 64 + i * 16 + aRowOff) * ROWB + ks * 32 + aColOff;
                asm volatile("ldmatrix.sync.aligned.m8n8.x4.shared.b16 {%0,%1,%2,%3}, [%4];"
                             : "=r"(af[i][0]), "=r"(af[i][1]), "=r"(af[i][2]), "=r"(af[i][3])
                             : "r"(addr));
            }
            uint32_t bf[4][2];
#pragma unroll
            for (int j = 0; j < 4; ++j) {
                uint32_t addr = bS[buf] + (wn * 32 + j * 8 + bRowOff) * ROWB + ks * 32 + bColOff;
                asm volatile("ldmatrix.sync.aligned.m8n8.x2.shared.b16 {%0,%1}, [%2];"
                             : "=r"(bf[j][0]), "=r"(bf[j][1]) : "r"(addr));
            }
#pragma unroll
            for (int i = 0; i < 4; ++i)
#pragma unroll
                for (int j = 0; j < 4; ++j) {
                    asm volatile(
                        "mma.sync.aligned.m16n8k16.row.col.f32.bf16.bf16.f32 "
                        "{%0,%1,%2,%3}, {%4,%5,%6,%7}, {%8,%9}, {%0,%1,%2,%3};"
                        : "+f"(acc[i][j][0]), "+f"(acc[i][j][1]),
                          "+f"(acc[i][j][2]), "+f"(acc[i][j][3])
                        : "r"(af[i][0]), "r"(af[i][1]), "r"(af[i][2]), "r"(af[i][3]),
                          "r"(bf[j][0]), "r"(bf[j][1]));
                }
        }
        __syncthreads();
        if (it + 2 < NIT) fill(buf, (it + 2) * HB_BK);
        else cp_commit();   // keep group accounting uniform
    }

    // epilogue: thread (lane) owns rows r, r+8 and col pair
#pragma unroll
    for (int i = 0; i < 4; ++i) {
        int row0 = rowBase + wm * 64 + i * 16 + (lane >> 2);
#pragma unroll
        for (int j = 0; j < 4; ++j) {
            int col = colBase + wn * 32 + j * 8 + (lane & 3) * 2;
            *reinterpret_cast<float2*>(C + (size_t)row0 * N + col) =
                make_float2(acc[i][j][0], acc[i][j][1]);
            *reinterpret_cast<float2*>(C + (size_t)(row0 + 8) * N + col) =
                make_float2(acc[i][j][2], acc[i][j][3]);
        }
    }
}

// ---------------- RoPE (neox style, in place on q and k of g_qkv) ----------------
__global__ void rope_kernel(const int* __restrict__ positions) {
    int idx = blockIdx.x * blockDim.x + threadIdx.x;
    const int total = TT * (NH + NKV) * (HD / 2);
    if (idx >= total) return;
    int d    = idx & (HD / 2 - 1);
    int tmp  = idx >> 7;
    int head = tmp % (NH + NKV);
    int t    = tmp / (NH + NKV);

    float pos = (float)positions[t];
    float inv = powf(10000.0f, -(float)d / 128.0f);
    float f   = pos * inv;
    float c   = cosf(f), s = sinf(f);

    float* base = g_qkv + (size_t)t * QKV_N + head * HD;
    float x1 = base[d];
    float x2 = base[d + HD / 2];
    base[d]          = x1 * c - x2 * s;
    base[d + HD / 2] = x2 * c + x1 * s;
}

// ---------------- Flash attention fp32, BQ=BK=64, HD=256 ----------------
#define QK_STRIDE 257
#define SS_STRIDE 65
#define ATTN_SMEM_FLOATS (3 * 64 * QK_STRIDE + 64 * SS_STRIDE + 3 * 64)
#define ATTN_SMEM_BYTES  (ATTN_SMEM_FLOATS * 4)

__global__ __launch_bounds__(256) void attn_kernel() {
    extern __shared__ float smf[];
    float* Qs  = smf;
    float* Ks  = Qs + 64 * QK_STRIDE;
    float* Vs  = Ks + 64 * QK_STRIDE;
    float* Ss  = Vs + 64 * QK_STRIDE;
    float* m_s = Ss + 64 * SS_STRIDE;
    float* l_s = m_s + 64;
    float* a_s = l_s + 64;

    const int tid = threadIdx.x;
    const int qt  = gridDim.x - 1 - blockIdx.x;
    const int h   = blockIdx.y;
    const int kh  = h >> 1;
    const int tr  = tid >> 4;
    const int tc  = tid & 15;

    const float SCALE = 0.0625f;
    const float CAP   = 50.0f;

    {
        const float* qg = g_qkv + (size_t)(qt * 64) * QKV_N + h * HD;
        for (int i = tid; i < 64 * 64; i += 256) {
            int r  = i >> 6;
            int c4 = (i & 63) << 2;
            float4 v = *reinterpret_cast<const float4*>(qg + (size_t)r * QKV_N + c4);
            float* dst = &Qs[r * QK_STRIDE + c4];
            dst[0] = v.x; dst[1] = v.y; dst[2] = v.z; dst[3] = v.w;
        }
    }
    if (tid < 64) { m_s[tid] = -1e30f; l_s[tid] = 0.f; }

    float acc[4][16];
#pragma unroll
    for (int i = 0; i < 4; ++i)
#pragma unroll
        for (int j = 0; j < 16; ++j) acc[i][j] = 0.f;

    for (int kt = 0; kt <= qt; ++kt) {
        __syncthreads();
        {
            const float* kg = g_qkv + (size_t)(kt * 64) * QKV_N + NH * HD + kh * HD;
            const float* vg = g_qkv + (size_t)(kt * 64) * QKV_N + (NH + NKV) * HD + kh * HD;
            for (int i = tid; i < 64 * 64; i += 256) {
                int r  = i >> 6;
                int c4 = (i & 63) << 2;
                float4 kv = *reinterpret_cast<const float4*>(kg + (size_t)r * QKV_N + c4);
                float* kd = &Ks[r * QK_STRIDE + c4];
                kd[0] = kv.x; kd[1] = kv.y; kd[2] = kv.z; kd[3] = kv.w;
                float4 vv = *reinterpret_cast<const float4*>(vg + (size_t)r * QKV_N + c4);
                float* vd = &Vs[r * QK_STRIDE + c4];
                vd[0] = vv.x; vd[1] = vv.y; vd[2] = vv.z; vd[3] = vv.w;
            }
        }
        __syncthreads();

        float s[4][4];
#pragma unroll
        for (int i = 0; i < 4; ++i)
#pragma unroll
            for (int j = 0; j < 4; ++j) s[i][j] = 0.f;

#pragma unroll 4
        for (int d = 0; d < HD; ++d) {
            float qv[4], kv[4];
#pragma unroll
            for (int i = 0; i < 4; ++i) qv[i] = Qs[(tr + 16 * i) * QK_STRIDE + d];
#pragma unroll
            for (int j = 0; j < 4; ++j) kv[j] = Ks[(tc + 16 * j) * QK_STRIDE + d];
#pragma unroll
            for (int i = 0; i < 4; ++i)
#pragma unroll
                for (int j = 0; j < 4; ++j) s[i][j] += qv[i] * kv[j];
        }

#pragma unroll
        for (int i = 0; i < 4; ++i) {
            int qrow = qt * 64 + tr + 16 * i;
#pragma unroll
            for (int j = 0; j < 4; ++j) {
                int kcol = kt * 64 + tc + 16 * j;
                float x = s[i][j] * SCALE;
                x = CAP * tanhf(x * (1.0f / CAP));
                if (kcol > qrow) x = -1e30f;
                Ss[(tr + 16 * i) * SS_STRIDE + (tc + 16 * j)] = x;
            }
        }
        __syncthreads();

        {
            const int row = tid >> 2;
            const int q4  = tid & 3;
            float* srow = &Ss[row * SS_STRIDE + q4 * 16];

            float mold = m_s[row];
            float mt = mold;
#pragma unroll
            for (int c = 0; c < 16; ++c) mt = fmaxf(mt, srow[c]);
            mt = fmaxf(mt, __shfl_xor_sync(0xFFFFFFFFu, mt, 1));
            mt = fmaxf(mt, __shfl_xor_sync(0xFFFFFFFFu, mt, 2));

            float sum = 0.f;
#pragma unroll
            for (int c = 0; c < 16; ++c) {
                float p = __expf(srow[c] - mt);
                srow[c] = p;
                sum += p;
            }
            sum += __shfl_xor_sync(0xFFFFFFFFu, sum, 1);
            sum += __shfl_xor_sync(0xFFFFFFFFu, sum, 2);

            if (q4 == 0) {
                float alpha = __expf(mold - mt);
                l_s[row] = l_s[row] * alpha + sum;
                m_s[row] = mt;
                a_s[row] = alpha;
            }
        }
        __syncthreads();

        float al[4];
#pragma unroll
        for (int i = 0; i < 4; ++i) al[i] = a_s[tr + 16 * i];
#pragma unroll
        for (int i = 0; i < 4; ++i)
#pragma unroll
            for (int j = 0; j < 16; ++j) acc[i][j] *= al[i];

#pragma unroll 4
        for (int k = 0; k < 64; ++k) {
            float p[4];
#pragma unroll
            for (int i = 0; i < 4; ++i) p[i] = Ss[(tr + 16 * i) * SS_STRIDE + k];
            float vv[16];
#pragma unroll
            for (int j = 0; j < 16; ++j) vv[j] = Vs[k * QK_STRIDE + tc + 16 * j];
#pragma unroll
            for (int i = 0; i < 4; ++i)
#pragma unroll
                for (int j = 0; j < 16; ++j) acc[i][j] += p[i] * vv[j];
        }
    }

    float invl[4];
#pragma unroll
    for (int i = 0; i < 4; ++i) invl[i] = 1.0f / l_s[tr + 16 * i];
#pragma unroll
    for (int i = 0; i < 4; ++i) {
        size_t row = (size_t)(qt * 64 + tr + 16 * i);
#pragma unroll
        for (int j = 0; j < 16; ++j)
            g_attn[row * OPROJ_K + h * HD + tc + 16 * j] = acc[i][j] * invl[i];
    }
}

// ---------------- launch ----------------
extern "C" void kernel_launch(void* const* d_in, const int* in_sizes, int n_in,
                              void* d_out, int out_size) {
    const int*   positions = (const int*)d_in[0];
    const float* hidden    = (const float*)d_in[1];
    const float* w_qkv     = (const float*)d_in[2];
    const float* w_o       = (const float*)d_in[3];
    float*       out       = (float*)d_out;

    float *qkv_ptr = nullptr, *attn_ptr = nullptr;
    __nv_bfloat16 *aq, *bq, *ao, *bo;
    cudaGetSymbolAddress((void**)&qkv_ptr, g_qkv);
    cudaGetSymbolAddress((void**)&attn_ptr, g_attn);
    cudaGetSymbolAddress((void**)&aq, g_Aq);
    cudaGetSymbolAddress((void**)&bq, g_Bq);
    cudaGetSymbolAddress((void**)&ao, g_Ao);
    cudaGetSymbolAddress((void**)&bo, g_Bo);

    cudaFuncSetAttribute(attn_kernel, cudaFuncAttributeMaxDynamicSharedMemorySize,
                         ATTN_SMEM_BYTES);

    // 1) split-convert inputs for QKV gemm
    conv_a_kernel<<<(TT * HID + 255) / 256, 256>>>(hidden, aq, TT, HID, K3Q);
    conv_bt_kernel<<<dim3(QKV_N / 32, HID / 32), dim3(32, 8)>>>(w_qkv, bq, HID, QKV_N, K3Q);

    // 2) QKV projection on tensor cores (HMMA): [T,K3Q] x [QKV_N,K3Q]^T
    gemm_mma_kernel<<<dim3(QKV_N / HB_BN, TT / HB_BM), 256>>>(aq, bq, qkv_ptr, QKV_N, K3Q);

    // 3) RoPE in place
    {
        int total = TT * (NH + NKV) * (HD / 2);
        rope_kernel<<<(total + 255) / 256, 256>>>(positions);
    }

    // 4) causal GQA attention with soft-cap
    attn_kernel<<<dim3(TT / 64, NH), 256, ATTN_SMEM_BYTES>>>();

    // 5) split-convert for O-proj gemm
    conv_a_kernel<<<(TT * OPROJ_K + 255) / 256, 256>>>(attn_ptr, ao, TT, OPROJ_K, K3O);
    conv_bt_kernel<<<dim3(HID / 32, OPROJ_K / 32), dim3(32, 8)>>>(w_o, bo, OPROJ_K, HID, K3O);

    // 6) output projection on tensor cores -> out
    gemm_mma_kernel<<<dim3(HID / HB_BN, TT / HB_BM), 256>>>(ao, bo, out, HID, K3O);
}

// round 11
// speedup vs baseline: 1.9266x; 1.3279x over previous
#include <cuda_runtime.h>
#include <cuda_bf16.h>
#include <math.h>
#include <stdint.h>

// ---------------- problem constants ----------------
#define TT   2048
#define HID  3584
#define NH   16
#define NKV  8
#define HD   256
#define QKV_N ((NH + 2 * NKV) * HD)   // 8192
#define OPROJ_K (NH * HD)             // 4096

#define K3Q (3 * HID)      // 10752
#define K3O (3 * OPROJ_K)  // 12288

__device__ __align__(16) float g_qkv[(size_t)TT * QKV_N];
__device__ __align__(16) float g_attn[(size_t)TT * OPROJ_K];
__device__ __align__(16) __nv_bfloat16 g_Aq[(size_t)TT * K3Q];
__device__ __align__(16) __nv_bfloat16 g_Bq[(size_t)QKV_N * K3Q];
__device__ __align__(16) __nv_bfloat16 g_Ao[(size_t)TT * K3O];
__device__ __align__(16) __nv_bfloat16 g_Bo[(size_t)HID * K3O];

__device__ __forceinline__ uint32_t smem_u32(const void* p) {
    uint32_t a;
    asm("{ .reg .u64 t; cvta.to.shared.u64 t, %1; cvt.u32.u64 %0, t; }" : "=r"(a) : "l"(p));
    return a;
}
__device__ __forceinline__ void cp_async16(uint32_t saddr, const void* gaddr) {
    asm volatile("cp.async.cg.shared.global [%0], [%1], 16;" :: "r"(saddr), "l"(gaddr));
}
__device__ __forceinline__ void cp_commit() {
    asm volatile("cp.async.commit_group;");
}
__device__ __forceinline__ void cp_wait1() {
    asm volatile("cp.async.wait_group 1;");
}
__device__ __forceinline__ void ldsm_x4(uint32_t addr, uint32_t* r) {
    asm volatile("ldmatrix.sync.aligned.m8n8.x4.shared.b16 {%0,%1,%2,%3}, [%4];"
                 : "=r"(r[0]), "=r"(r[1]), "=r"(r[2]), "=r"(r[3]) : "r"(addr));
}
__device__ __forceinline__ void ldsm_x2(uint32_t addr, uint32_t* r) {
    asm volatile("ldmatrix.sync.aligned.m8n8.x2.shared.b16 {%0,%1}, [%2];"
                 : "=r"(r[0]), "=r"(r[1]) : "r"(addr));
}
__device__ __forceinline__ void ldsm_x2t(uint32_t addr, uint32_t* r) {
    asm volatile("ldmatrix.sync.aligned.m8n8.x2.trans.shared.b16 {%0,%1}, [%2];"
                 : "=r"(r[0]), "=r"(r[1]) : "r"(addr));
}
__device__ __forceinline__ void mma16816(float* d, uint32_t a0, uint32_t a1, uint32_t a2,
                                         uint32_t a3, uint32_t b0, uint32_t b1) {
    asm volatile(
        "mma.sync.aligned.m16n8k16.row.col.f32.bf16.bf16.f32 "
        "{%0,%1,%2,%3}, {%4,%5,%6,%7}, {%8,%9}, {%0,%1,%2,%3};"
        : "+f"(d[0]), "+f"(d[1]), "+f"(d[2]), "+f"(d[3])
        : "r"(a0), "r"(a1), "r"(a2), "r"(a3), "r"(b0), "r"(b1));
}
__device__ __forceinline__ void split2(float x, float y, uint32_t& hi, uint32_t& lo) {
    __nv_bfloat162 h2, l2;
    h2.x = __float2bfloat16(x);
    h2.y = __float2bfloat16(y);
    l2.x = __float2bfloat16(x - __bfloat162float(h2.x));
    l2.y = __float2bfloat16(y - __bfloat162float(h2.y));
    hi = *reinterpret_cast<uint32_t*>(&h2);
    lo = *reinterpret_cast<uint32_t*>(&l2);
}

// ============================================================
// conversion kernels: fp32 -> bf16 hi/lo split panels (unchanged)
// ============================================================
__global__ void conv_a_kernel(const float* __restrict__ A, __nv_bfloat16* __restrict__ A3,
                              int M, int K, int K3) {
    int idx = blockIdx.x * blockDim.x + threadIdx.x;
    if (idx >= M * K) return;
    int m = idx / K, k = idx - m * K;
    float x = A[idx];
    __nv_bfloat16 hi = __float2bfloat16(x);
    __nv_bfloat16 lo = __float2bfloat16(x - __bfloat162float(hi));
    size_t base = (size_t)m * K3;
    A3[base + k]         = hi;
    A3[base + K + k]     = lo;
    A3[base + 2 * K + k] = hi;
}

__global__ __launch_bounds__(256) void conv_bt_kernel(const float* __restrict__ W,
                                                      __nv_bfloat16* __restrict__ Bt,
                                                      int K, int N, int K3) {
    __shared__ float t[32][33];
    int n0 = blockIdx.x * 32, k0 = blockIdx.y * 32;
    int tx = threadIdx.x, ty = threadIdx.y;
#pragma unroll
    for (int i = 0; i < 4; ++i)
        t[ty + 8 * i][tx] = W[(size_t)(k0 + ty + 8 * i) * N + n0 + tx];
    __syncthreads();
#pragma unroll
    for (int i = 0; i < 4; ++i) {
        int n = n0 + ty + 8 * i;
        int k = k0 + tx;
        float x = t[tx][ty + 8 * i];
        __nv_bfloat16 hi = __float2bfloat16(x);
        __nv_bfloat16 lo = __float2bfloat16(x - __bfloat162float(hi));
        size_t base = (size_t)n * K3;
        Bt[base + k]         = hi;
        Bt[base + K + k]     = hi;
        Bt[base + 2 * K + k] = lo;
    }
}

// ============================================================
// HMMA bf16 GEMM (unchanged, validated R8)
// ============================================================
#define HB_BM 128
#define HB_BN 128
#define HB_BK 32
#define ROWB 80

__global__ __launch_bounds__(256) void gemm_mma_kernel(const __nv_bfloat16* __restrict__ Ap,
                                                       const __nv_bfloat16* __restrict__ Bp,
                                                       float* __restrict__ C,
                                                       int N, int K3) {
    __shared__ __align__(16) char As[2][128 * ROWB];
    __shared__ __align__(16) char Bs[2][128 * ROWB];

    const int tid  = threadIdx.x;
    const int lane = tid & 31;
    const int wid  = tid >> 5;
    const int wm   = wid & 1;
    const int wn   = wid >> 1;
    const int rowBase = blockIdx.y * HB_BM;
    const int colBase = blockIdx.x * HB_BN;

    const uint32_t aS[2] = {smem_u32(As[0]), smem_u32(As[1])};
    const uint32_t bS[2] = {smem_u32(Bs[0]), smem_u32(Bs[1])};

    const __nv_bfloat16* Ag = Ap + (size_t)rowBase * K3;
    const __nv_bfloat16* Bg = Bp + (size_t)colBase * K3;

    auto fill = [&](int buf, int k0) {
#pragma unroll
        for (int u = 0; u < 2; ++u) {
            int ch = tid + u * 256;
            int r = ch >> 2, c = ch & 3;
            cp_async16(aS[buf] + r * ROWB + c * 16, Ag + (size_t)r * K3 + k0 + c * 8);
        }
#pragma unroll
        for (int u = 0; u < 2; ++u) {
            int ch = tid + u * 256;
            int r = ch >> 2, c = ch & 3;
            cp_async16(bS[buf] + r * ROWB + c * 16, Bg + (size_t)r * K3 + k0 + c * 8);
        }
        cp_commit();
    };

    float acc[4][4][4];
#pragma unroll
    for (int i = 0; i < 4; ++i)
#pragma unroll
        for (int j = 0; j < 4; ++j)
#pragma unroll
            for (int e = 0; e < 4; ++e) acc[i][j][e] = 0.f;

    const int NIT = K3 / HB_BK;
    fill(0, 0);
    fill(1, HB_BK);

    const int aRowOff = (lane & 7) + ((lane >> 3) & 1) * 8;
    const int aColOff = (lane >> 4) * 16;
    const int lnb     = lane & 15;
    const int bRowOff = lnb & 7;
    const int bColOff = (lnb >> 3) * 16;

    for (int it = 0; it < NIT; ++it) {
        const int buf = it & 1;
        cp_wait1();
        __syncthreads();

#pragma unroll
        for (int ks = 0; ks < 2; ++ks) {
            uint32_t af[4][4];
#pragma unroll
            for (int i = 0; i < 4; ++i)
                ldsm_x4(aS[buf] + (wm * 64 + i * 16 + aRowOff) * ROWB + ks * 32 + aColOff,
                        af[i]);
            uint32_t bf[4][2];
#pragma unroll
            for (int j = 0; j < 4; ++j)
                ldsm_x2(bS[buf] + (wn * 32 + j * 8 + bRowOff) * ROWB + ks * 32 + bColOff,
                        bf[j]);
#pragma unroll
            for (int i = 0; i < 4; ++i)
#pragma unroll
                for (int j = 0; j < 4; ++j)
                    mma16816(acc[i][j], af[i][0], af[i][1], af[i][2], af[i][3],
                             bf[j][0], bf[j][1]);
        }
        __syncthreads();
        if (it + 2 < NIT) fill(buf, (it + 2) * HB_BK);
        else cp_commit();
    }

#pragma unroll
    for (int i = 0; i < 4; ++i) {
        int row0 = rowBase + wm * 64 + i * 16 + (lane >> 2);
#pragma unroll
        for (int j = 0; j < 4; ++j) {
            int col = colBase + wn * 32 + j * 8 + (lane & 3) * 2;
            *reinterpret_cast<float2*>(C + (size_t)row0 * N + col) =
                make_float2(acc[i][j][0], acc[i][j][1]);
            *reinterpret_cast<float2*>(C + (size_t)(row0 + 8) * N + col) =
                make_float2(acc[i][j][2], acc[i][j][3]);
        }
    }
}

// ---------------- RoPE (unchanged) ----------------
__global__ void rope_kernel(const int* __restrict__ positions) {
    int idx = blockIdx.x * blockDim.x + threadIdx.x;
    const int total = TT * (NH + NKV) * (HD / 2);
    if (idx >= total) return;
    int d    = idx & (HD / 2 - 1);
    int tmp  = idx >> 7;
    int head = tmp % (NH + NKV);
    int t    = tmp / (NH + NKV);

    float pos = (float)positions[t];
    float inv = powf(10000.0f, -(float)d / 128.0f);
    float f   = pos * inv;
    float c   = cosf(f), s = sinf(f);

    float* base = g_qkv + (size_t)t * QKV_N + head * HD;
    float x1 = base[d];
    float x2 = base[d + HD / 2];
    base[d]          = x1 * c - x2 * s;
    base[d + HD / 2] = x2 * c + x1 * s;
}

// ============================================================
// HMMA flash attention: BQ=BK=64, HD=256, bf16 hi/lo split.
// 256 threads = 8 warps: wm=wid&3 (m16 rows), wn=wid>>2 (S n32 / O n128).
// smem byte offsets (row strides: 528B for 256-wide bf16 tiles,
// 144B for 64-wide P tiles, 264B for S fp32 [66 floats]):
// ============================================================
#define ARS 528
#define PRS 144
#define SRS 264
#define OQH 0
#define OQL 33792
#define OKH 67584
#define OKL 101376
#define OVH 135168
#define OVL 168960
#define OSP 202752                 // S fp32 (16896B) overlaid by Phi
#define OPL (OSP + 9216)           // Plo
#define OMLA (OSP + 18432)         // m(256) l(256) a(256)
#define ATTN2_SMEM (OMLA + 768)    // 221952

__global__ __launch_bounds__(256) void attn_mma_kernel() {
    extern __shared__ char sm[];
    const uint32_t SB = smem_u32(sm);

    float* m_s = (float*)(sm + OMLA);
    float* l_s = m_s + 64;
    float* a_s = l_s + 64;

    const int tid  = threadIdx.x;
    const int lane = tid & 31;
    const int wid  = tid >> 5;
    const int wm   = wid & 3;
    const int wn   = wid >> 2;
    const int qt   = gridDim.x - 1 - blockIdx.x;
    const int h    = blockIdx.y;
    const int kh   = h >> 1;

    const float SCALE = 0.0625f;

    // ---- load Q tile, split hi/lo ----
    {
        const float* qg = g_qkv + (size_t)(qt * 64) * QKV_N + h * HD;
#pragma unroll
        for (int u = 0; u < 16; ++u) {
            int i = tid + u * 256;
            int r = i >> 6, c4 = (i & 63) << 2;
            float4 v = *reinterpret_cast<const float4*>(qg + (size_t)r * QKV_N + c4);
            uint32_t h0, l0, h1, l1;
            split2(v.x, v.y, h0, l0);
            split2(v.z, v.w, h1, l1);
            *reinterpret_cast<uint2*>(sm + OQH + r * ARS + c4 * 2) = make_uint2(h0, h1);
            *reinterpret_cast<uint2*>(sm + OQL + r * ARS + c4 * 2) = make_uint2(l0, l1);
        }
    }
    if (tid < 64) { m_s[tid] = -1e30f; l_s[tid] = 0.f; }

    float oacc[16][4];
#pragma unroll
    for (int j = 0; j < 16; ++j)
#pragma unroll
        for (int e = 0; e < 4; ++e) oacc[j][e] = 0.f;

    const int aRowOff = (lane & 7) + ((lane >> 3) & 1) * 8;
    const int aColOff = (lane >> 4) * 16;
    const int lnb = lane & 15;
    const int bRow = lnb & 7;
    const int bCol = (lnb >> 3) * 16;
    const int r0 = wm * 16 + (lane >> 2);

    for (int kt = 0; kt <= qt; ++kt) {
        __syncthreads();   // prior K/V/P reads done; Q + m/l init visible
        // ---- load K,V tiles, split hi/lo ----
        {
            const float* kg = g_qkv + (size_t)(kt * 64) * QKV_N + NH * HD + kh * HD;
            const float* vg = kg + NKV * HD;
#pragma unroll
            for (int u = 0; u < 16; ++u) {
                int i = tid + u * 256;
                int r = i >> 6, c4 = (i & 63) << 2;
                float4 kv = *reinterpret_cast<const float4*>(kg + (size_t)r * QKV_N + c4);
                uint32_t h0, l0, h1, l1;
                split2(kv.x, kv.y, h0, l0);
                split2(kv.z, kv.w, h1, l1);
                *reinterpret_cast<uint2*>(sm + OKH + r * ARS + c4 * 2) = make_uint2(h0, h1);
                *reinterpret_cast<uint2*>(sm + OKL + r * ARS + c4 * 2) = make_uint2(l0, l1);
                float4 vv = *reinterpret_cast<const float4*>(vg + (size_t)r * QKV_N + c4);
                split2(vv.x, vv.y, h0, l0);
                split2(vv.z, vv.w, h1, l1);
                *reinterpret_cast<uint2*>(sm + OVH + r * ARS + c4 * 2) = make_uint2(h0, h1);
                *reinterpret_cast<uint2*>(sm + OVL + r * ARS + c4 * 2) = make_uint2(l0, l1);
            }
        }
        __syncthreads();

        // ---- S = Q K^T (3 split passes) ----
        float sacc[4][4];
#pragma unroll
        for (int j = 0; j < 4; ++j)
#pragma unroll
            for (int e = 0; e < 4; ++e) sacc[j][e] = 0.f;

#pragma unroll 1
        for (int pass = 0; pass < 3; ++pass) {
            const uint32_t Ab = SB + ((pass == 1) ? OQL : OQH);
            const uint32_t Bb = SB + ((pass == 2) ? OKL : OKH);
#pragma unroll 4
            for (int ks = 0; ks < 16; ++ks) {
                uint32_t af[4];
                ldsm_x4(Ab + (wm * 16 + aRowOff) * ARS + ks * 32 + aColOff, af);
#pragma unroll
                for (int j = 0; j < 4; ++j) {
                    uint32_t bf[2];
                    ldsm_x2(Bb + (wn * 32 + j * 8 + bRow) * ARS + ks * 32 + bCol, bf);
                    mma16816(sacc[j], af[0], af[1], af[2], af[3], bf[0], bf[1]);
                }
            }
        }

        // ---- scale + softcap + causal mask, store S ----
#pragma unroll
        for (int j = 0; j < 4; ++j) {
            int colb = wn * 32 + j * 8 + (lane & 3) * 2;
            int kc0 = kt * 64 + colb;
#pragma unroll
            for (int hf = 0; hf < 2; ++hf) {
                int r = r0 + hf * 8;
                int qrow = qt * 64 + r;
                float x0 = 50.0f * tanhf(sacc[j][hf * 2] * SCALE * 0.02f);
                float x1 = 50.0f * tanhf(sacc[j][hf * 2 + 1] * SCALE * 0.02f);
                if (kc0 > qrow)     x0 = -1e30f;
                if (kc0 + 1 > qrow) x1 = -1e30f;
                *reinterpret_cast<float2*>(sm + OSP + r * SRS + colb * 4) =
                    make_float2(x0, x1);
            }
        }
        __syncthreads();

        // ---- softmax: 4 threads per row; keep p in regs across barrier ----
        const int row = tid >> 2;
        const int q4  = tid & 3;
        float p[16];
        {
            const float* srow = (const float*)(sm + OSP + row * SRS) + q4 * 16;
            float mold = m_s[row];
            float mt = mold;
#pragma unroll
            for (int c = 0; c < 16; ++c) mt = fmaxf(mt, srow[c]);
            mt = fmaxf(mt, __shfl_xor_sync(0xFFFFFFFFu, mt, 1));
            mt = fmaxf(mt, __shfl_xor_sync(0xFFFFFFFFu, mt, 2));
            float sum = 0.f;
#pragma unroll
            for (int c = 0; c < 16; ++c) {
                p[c] = __expf(srow[c] - mt);
                sum += p[c];
            }
            sum += __shfl_xor_sync(0xFFFFFFFFu, sum, 1);
            sum += __shfl_xor_sync(0xFFFFFFFFu, sum, 2);
            if (q4 == 0) {
                float alpha = __expf(mold - mt);
                l_s[row] = l_s[row] * alpha + sum;
                m_s[row] = mt;
                a_s[row] = alpha;
            }
        }
        __syncthreads();   // all S reads done; P overlay now safe

        // ---- write P hi/lo (overlays S region) ----
        {
            __nv_bfloat16* ph = (__nv_bfloat16*)(sm + OSP + row * PRS) + q4 * 16;
            __nv_bfloat16* pl = (__nv_bfloat16*)(sm + OPL + row * PRS) + q4 * 16;
#pragma unroll
            for (int c = 0; c < 16; ++c) {
                __nv_bfloat16 hp = __float2bfloat16(p[c]);
                ph[c] = hp;
                pl[c] = __float2bfloat16(p[c] - __bfloat162float(hp));
            }
        }
        // ---- rescale O accumulators by alpha ----
        {
            float al0 = a_s[r0], al1 = a_s[r0 + 8];
#pragma unroll
            for (int j = 0; j < 16; ++j) {
                oacc[j][0] *= al0; oacc[j][1] *= al0;
                oacc[j][2] *= al1; oacc[j][3] *= al1;
            }
        }
        __syncthreads();

        // ---- O += P V (3 split passes; B via ldmatrix.trans on V[t][d]) ----
#pragma unroll 1
        for (int pass = 0; pass < 3; ++pass) {
            const uint32_t Ab = SB + ((pass == 1) ? OPL : OSP);
            const uint32_t Bb = SB + ((pass == 2) ? OVL : OVH);
#pragma unroll
            for (int ks = 0; ks < 4; ++ks) {
                uint32_t af[4];
                ldsm_x4(Ab + (wm * 16 + aRowOff) * PRS + ks * 32 + aColOff, af);
#pragma unroll
                for (int j = 0; j < 16; ++j) {
                    uint32_t bf[2];
                    ldsm_x2t(Bb + (ks * 16 + lnb) * ARS + (wn * 128 + j * 8) * 2, bf);
                    mma16816(oacc[j], af[0], af[1], af[2], af[3], bf[0], bf[1]);
                }
            }
        }
    }

    // ---- epilogue: O /= l, write g_attn ----
    {
        float il0 = 1.0f / l_s[r0];
        float il1 = 1.0f / l_s[r0 + 8];
        size_t row0 = (size_t)(qt * 64 + r0);
#pragma unroll
        for (int j = 0; j < 16; ++j) {
            int col = h * HD + wn * 128 + j * 8 + (lane & 3) * 2;
            *reinterpret_cast<float2*>(g_attn + row0 * OPROJ_K + col) =
                make_float2(oacc[j][0] * il0, oacc[j][1] * il0);
            *reinterpret_cast<float2*>(g_attn + (row0 + 8) * OPROJ_K + col) =
                make_float2(oacc[j][2] * il1, oacc[j][3] * il1);
        }
    }
}

// ---------------- launch ----------------
extern "C" void kernel_launch(void* const* d_in, const int* in_sizes, int n_in,
                              void* d_out, int out_size) {
    const int*   positions = (const int*)d_in[0];
    const float* hidden    = (const float*)d_in[1];
    const float* w_qkv     = (const float*)d_in[2];
    const float* w_o       = (const float*)d_in[3];
    float*       out       = (float*)d_out;

    float *qkv_ptr = nullptr, *attn_ptr = nullptr;
    __nv_bfloat16 *aq, *bq, *ao, *bo;
    cudaGetSymbolAddress((void**)&qkv_ptr, g_qkv);
    cudaGetSymbolAddress((void**)&attn_ptr, g_attn);
    cudaGetSymbolAddress((void**)&aq, g_Aq);
    cudaGetSymbolAddress((void**)&bq, g_Bq);
    cudaGetSymbolAddress((void**)&ao, g_Ao);
    cudaGetSymbolAddress((void**)&bo, g_Bo);

    cudaFuncSetAttribute(attn_mma_kernel, cudaFuncAttributeMaxDynamicSharedMemorySize,
                         ATTN2_SMEM);

    // 1) split-convert inputs for QKV gemm
    conv_a_kernel<<<(TT * HID + 255) / 256, 256>>>(hidden, aq, TT, HID, K3Q);
    conv_bt_kernel<<<dim3(QKV_N / 32, HID / 32), dim3(32, 8)>>>(w_qkv, bq, HID, QKV_N, K3Q);

    // 2) QKV projection (HMMA)
    gemm_mma_kernel<<<dim3(QKV_N / HB_BN, TT / HB_BM), 256>>>(aq, bq, qkv_ptr, QKV_N, K3Q);

    // 3) RoPE in place
    {
        int total = TT * (NH + NKV) * (HD / 2);
        rope_kernel<<<(total + 255) / 256, 256>>>(positions);
    }

    // 4) causal GQA attention with soft-cap (HMMA flash)
    attn_mma_kernel<<<dim3(TT / 64, NH), 256, ATTN2_SMEM>>>();

    // 5) split-convert for O-proj gemm
    conv_a_kernel<<<(TT * OPROJ_K + 255) / 256, 256>>>(attn_ptr, ao, TT, OPROJ_K, K3O);
    conv_bt_kernel<<<dim3(HID / 32, OPROJ_K / 32), dim3(32, 8)>>>(w_o, bo, OPROJ_K, HID, K3O);

    // 6) output projection (HMMA) -> out
    gemm_mma_kernel<<<dim3(HID / HB_BN, TT / HB_BM), 256>>>(ao, bo, out, HID, K3O);
}

// round 13
// speedup vs baseline: 1.9623x; 1.0185x over previous
#include <cuda_runtime.h>
#include <cuda_bf16.h>
#include <math.h>
#include <stdint.h>

// ---------------- problem constants ----------------
#define TT   2048
#define HID  3584
#define NH   16
#define NKV  8
#define HD   256
#define QKV_N ((NH + 2 * NKV) * HD)   // 8192
#define OPROJ_K (NH * HD)             // 4096

#define K3Q (3 * HID)      // 10752
#define K3O (3 * OPROJ_K)  // 12288

__device__ __align__(16) float g_qkv[(size_t)TT * QKV_N];                 // 64 MB
__device__ __align__(16) __nv_bfloat16 g_qhl[2 * (size_t)TT * QKV_N];     // 64 MB (hi | lo)
__device__ __align__(16) __nv_bfloat16 g_Aq[(size_t)TT * K3Q];
__device__ __align__(16) __nv_bfloat16 g_Bq[(size_t)QKV_N * K3Q];
__device__ __align__(16) __nv_bfloat16 g_Ao[(size_t)TT * K3O];
__device__ __align__(16) __nv_bfloat16 g_Bo[(size_t)HID * K3O];

__device__ __forceinline__ uint32_t smem_u32(const void* p) {
    uint32_t a;
    asm("{ .reg .u64 t; cvta.to.shared.u64 t, %1; cvt.u32.u64 %0, t; }" : "=r"(a) : "l"(p));
    return a;
}
__device__ __forceinline__ void cp_async16(uint32_t saddr, const void* gaddr) {
    asm volatile("cp.async.cg.shared.global [%0], [%1], 16;" :: "r"(saddr), "l"(gaddr));
}
__device__ __forceinline__ void cp_commit() {
    asm volatile("cp.async.commit_group;");
}
__device__ __forceinline__ void cp_wait1() {
    asm volatile("cp.async.wait_group 1;");
}
__device__ __forceinline__ void cp_wait0() {
    asm volatile("cp.async.wait_group 0;");
}
__device__ __forceinline__ void ldsm_x4(uint32_t addr, uint32_t* r) {
    asm volatile("ldmatrix.sync.aligned.m8n8.x4.shared.b16 {%0,%1,%2,%3}, [%4];"
                 : "=r"(r[0]), "=r"(r[1]), "=r"(r[2]), "=r"(r[3]) : "r"(addr));
}
__device__ __forceinline__ void ldsm_x2(uint32_t addr, uint32_t* r) {
    asm volatile("ldmatrix.sync.aligned.m8n8.x2.shared.b16 {%0,%1}, [%2];"
                 : "=r"(r[0]), "=r"(r[1]) : "r"(addr));
}
__device__ __forceinline__ void ldsm_x2t(uint32_t addr, uint32_t* r) {
    asm volatile("ldmatrix.sync.aligned.m8n8.x2.trans.shared.b16 {%0,%1}, [%2];"
                 : "=r"(r[0]), "=r"(r[1]) : "r"(addr));
}
__device__ __forceinline__ void mma16816(float* d, uint32_t a0, uint32_t a1, uint32_t a2,
                                         uint32_t a3, uint32_t b0, uint32_t b1) {
    asm volatile(
        "mma.sync.aligned.m16n8k16.row.col.f32.bf16.bf16.f32 "
        "{%0,%1,%2,%3}, {%4,%5,%6,%7}, {%8,%9}, {%0,%1,%2,%3};"
        : "+f"(d[0]), "+f"(d[1]), "+f"(d[2]), "+f"(d[3])
        : "r"(a0), "r"(a1), "r"(a2), "r"(a3), "r"(b0), "r"(b1));
}
__device__ __forceinline__ void split2(float x, float y, uint32_t& hi, uint32_t& lo) {
    __nv_bfloat162 h2, l2;
    h2.x = __float2bfloat16(x);
    h2.y = __float2bfloat16(y);
    l2.x = __float2bfloat16(x - __bfloat162float(h2.x));
    l2.y = __float2bfloat16(y - __bfloat162float(h2.y));
    hi = *reinterpret_cast<uint32_t*>(&h2);
    lo = *reinterpret_cast<uint32_t*>(&l2);
}

// ============================================================
// conversion kernels: fp32 -> bf16 hi/lo split panels
// ============================================================
__global__ void conv_a_kernel(const float* __restrict__ A, __nv_bfloat16* __restrict__ A3,
                              int M, int K, int K3) {
    int idx = blockIdx.x * blockDim.x + threadIdx.x;
    if (idx >= M * K) return;
    int m = idx / K, k = idx - m * K;
    float x = A[idx];
    __nv_bfloat16 hi = __float2bfloat16(x);
    __nv_bfloat16 lo = __float2bfloat16(x - __bfloat162float(hi));
    size_t base = (size_t)m * K3;
    A3[base + k]         = hi;
    A3[base + K + k]     = lo;
    A3[base + 2 * K + k] = hi;
}

__global__ __launch_bounds__(256) void conv_bt_kernel(const float* __restrict__ W,
                                                      __nv_bfloat16* __restrict__ Bt,
                                                      int K, int N, int K3) {
    __shared__ float t[32][33];
    int n0 = blockIdx.x * 32, k0 = blockIdx.y * 32;
    int tx = threadIdx.x, ty = threadIdx.y;
#pragma unroll
    for (int i = 0; i < 4; ++i)
        t[ty + 8 * i][tx] = W[(size_t)(k0 + ty + 8 * i) * N + n0 + tx];
    __syncthreads();
#pragma unroll
    for (int i = 0; i < 4; ++i) {
        int n = n0 + ty + 8 * i;
        int k = k0 + tx;
        float x = t[tx][ty + 8 * i];
        __nv_bfloat16 hi = __float2bfloat16(x);
        __nv_bfloat16 lo = __float2bfloat16(x - __bfloat162float(hi));
        size_t base = (size_t)n * K3;
        Bt[base + k]         = hi;
        Bt[base + K + k]     = hi;
        Bt[base + 2 * K + k] = lo;
    }
}

// ============================================================
// HMMA bf16 GEMM (unchanged, validated R8)
// ============================================================
#define HB_BM 128
#define HB_BN 128
#define HB_BK 32
#define ROWB 80

__global__ __launch_bounds__(256) void gemm_mma_kernel(const __nv_bfloat16* __restrict__ Ap,
                                                       const __nv_bfloat16* __restrict__ Bp,
                                                       float* __restrict__ C,
                                                       int N, int K3) {
    __shared__ __align__(16) char As[2][128 * ROWB];
    __shared__ __align__(16) char Bs[2][128 * ROWB];

    const int tid  = threadIdx.x;
    const int lane = tid & 31;
    const int wid  = tid >> 5;
    const int wm   = wid & 1;
    const int wn   = wid >> 1;
    const int rowBase = blockIdx.y * HB_BM;
    const int colBase = blockIdx.x * HB_BN;

    const uint32_t aS[2] = {smem_u32(As[0]), smem_u32(As[1])};
    const uint32_t bS[2] = {smem_u32(Bs[0]), smem_u32(Bs[1])};

    const __nv_bfloat16* Ag = Ap + (size_t)rowBase * K3;
    const __nv_bfloat16* Bg = Bp + (size_t)colBase * K3;

    auto fill = [&](int buf, int k0) {
#pragma unroll
        for (int u = 0; u < 2; ++u) {
            int ch = tid + u * 256;
            int r = ch >> 2, c = ch & 3;
            cp_async16(aS[buf] + r * ROWB + c * 16, Ag + (size_t)r * K3 + k0 + c * 8);
        }
#pragma unroll
        for (int u = 0; u < 2; ++u) {
            int ch = tid + u * 256;
            int r = ch >> 2, c = ch & 3;
            cp_async16(bS[buf] + r * ROWB + c * 16, Bg + (size_t)r * K3 + k0 + c * 8);
        }
        cp_commit();
    };

    float acc[4][4][4];
#pragma unroll
    for (int i = 0; i < 4; ++i)
#pragma unroll
        for (int j = 0; j < 4; ++j)
#pragma unroll
            for (int e = 0; e < 4; ++e) acc[i][j][e] = 0.f;

    const int NIT = K3 / HB_BK;
    fill(0, 0);
    fill(1, HB_BK);

    const int aRowOff = (lane & 7) + ((lane >> 3) & 1) * 8;
    const int aColOff = (lane >> 4) * 16;
    const int lnb     = lane & 15;
    const int bRowOff = lnb & 7;
    const int bColOff = (lnb >> 3) * 16;

    for (int it = 0; it < NIT; ++it) {
        const int buf = it & 1;
        cp_wait1();
        __syncthreads();

#pragma unroll
        for (int ks = 0; ks < 2; ++ks) {
            uint32_t af[4][4];
#pragma unroll
            for (int i = 0; i < 4; ++i)
                ldsm_x4(aS[buf] + (wm * 64 + i * 16 + aRowOff) * ROWB + ks * 32 + aColOff,
                        af[i]);
            uint32_t bf[4][2];
#pragma unroll
            for (int j = 0; j < 4; ++j)
                ldsm_x2(bS[buf] + (wn * 32 + j * 8 + bRowOff) * ROWB + ks * 32 + bColOff,
                        bf[j]);
#pragma unroll
            for (int i = 0; i < 4; ++i)
#pragma unroll
                for (int j = 0; j < 4; ++j)
                    mma16816(acc[i][j], af[i][0], af[i][1], af[i][2], af[i][3],
                             bf[j][0], bf[j][1]);
        }
        __syncthreads();
        if (it + 2 < NIT) fill(buf, (it + 2) * HB_BK);
        else cp_commit();
    }

#pragma unroll
    for (int i = 0; i < 4; ++i) {
        int row0 = rowBase + wm * 64 + i * 16 + (lane >> 2);
#pragma unroll
        for (int j = 0; j < 4; ++j) {
            int col = colBase + wn * 32 + j * 8 + (lane & 3) * 2;
            *reinterpret_cast<float2*>(C + (size_t)row0 * N + col) =
                make_float2(acc[i][j][0], acc[i][j][1]);
            *reinterpret_cast<float2*>(C + (size_t)(row0 + 8) * N + col) =
                make_float2(acc[i][j][2], acc[i][j][3]);
        }
    }
}

// ============================================================
// fused RoPE + bf16 hi/lo split: g_qkv fp32 -> g_qhl (hi | lo)
// one thread per (t, head, d<128) pair; v heads pass through un-rotated.
// ============================================================
__global__ void rope_split_kernel(const int* __restrict__ positions) {
    int idx = blockIdx.x * blockDim.x + threadIdx.x;
    const int total = TT * (NH + 2 * NKV) * (HD / 2);
    if (idx >= total) return;
    int d    = idx & (HD / 2 - 1);
    int tmp  = idx >> 7;
    int head = tmp % (NH + 2 * NKV);
    int t    = tmp / (NH + 2 * NKV);

    const float* base = g_qkv + (size_t)t * QKV_N + head * HD;
    float x1 = base[d];
    float x2 = base[d + HD / 2];
    float y1 = x1, y2 = x2;
    if (head < NH + NKV) {
        float pos = (float)positions[t];
        float inv = powf(10000.0f, -(float)d / 128.0f);
        float f   = pos * inv;
        float c   = cosf(f), s = sinf(f);
        y1 = x1 * c - x2 * s;
        y2 = x2 * c + x1 * s;
    }
    size_t o = (size_t)t * QKV_N + head * HD;
    const size_t LOFF = (size_t)TT * QKV_N;
    __nv_bfloat16 h1 = __float2bfloat16(y1);
    __nv_bfloat16 h2 = __float2bfloat16(y2);
    g_qhl[o + d]                     = h1;
    g_qhl[o + d + HD / 2]            = h2;
    g_qhl[LOFF + o + d]              = __float2bfloat16(y1 - __bfloat162float(h1));
    g_qhl[LOFF + o + d + HD / 2]     = __float2bfloat16(y2 - __bfloat162float(h2));
}

// ============================================================
// HMMA flash attention (validated R11) — now cp.async loads of
// precomputed bf16 hi/lo tiles; epilogue writes O-proj A' panels.
// ============================================================
#define ARS 528
#define PRS 144
#define SRS 264
#define OQH 0
#define OQL 33792
#define OKH 67584
#define OKL 101376
#define OVH 135168
#define OVL 168960
#define OSP 202752                 // S fp32 (16896B) overlaid by Phi
#define OPL (OSP + 9216)           // Plo
#define OMLA (OSP + 18432)         // m(256) l(256) a(256)
#define ATTN2_SMEM (OMLA + 768)    // 221952

__global__ __launch_bounds__(256) void attn_mma_kernel() {
    extern __shared__ char sm[];
    const uint32_t SB = smem_u32(sm);

    float* m_s = (float*)(sm + OMLA);
    float* l_s = m_s + 64;
    float* a_s = l_s + 64;

    const int tid  = threadIdx.x;
    const int lane = tid & 31;
    const int wid  = tid >> 5;
    const int wm   = wid & 3;
    const int wn   = wid >> 2;
    const int qt   = gridDim.x - 1 - blockIdx.x;
    const int h    = blockIdx.y;
    const int kh   = h >> 1;

    const float SCALE = 0.0625f;
    const size_t LOFF = (size_t)TT * QKV_N;

    // load one 64x256 bf16 tile (row stride QKV_N) into smem at ARS stride
    auto load_tile = [&](uint32_t smoff, const __nv_bfloat16* gsrc) {
#pragma unroll
        for (int u = 0; u < 8; ++u) {
            int ch = tid + u * 256;
            int r = ch >> 5, c = ch & 31;
            cp_async16(SB + smoff + r * ARS + c * 16, gsrc + (size_t)r * QKV_N + c * 8);
        }
    };

    // ---- load Q tile hi/lo ----
    {
        const __nv_bfloat16* qh = g_qhl + (size_t)(qt * 64) * QKV_N + h * HD;
        load_tile(OQH, qh);
        load_tile(OQL, qh + LOFF);
        cp_commit();
    }
    if (tid < 64) { m_s[tid] = -1e30f; l_s[tid] = 0.f; }
    cp_wait0();

    float oacc[16][4];
#pragma unroll
    for (int j = 0; j < 16; ++j)
#pragma unroll
        for (int e = 0; e < 4; ++e) oacc[j][e] = 0.f;

    const int aRowOff = (lane & 7) + ((lane >> 3) & 1) * 8;
    const int aColOff = (lane >> 4) * 16;
    const int lnb = lane & 15;
    const int bRow = lnb & 7;
    const int bCol = (lnb >> 3) * 16;
    const int r0 = wm * 16 + (lane >> 2);

    for (int kt = 0; kt <= qt; ++kt) {
        __syncthreads();   // prior K/V/P reads done; Q + m/l init visible
        // ---- cp.async K,V hi/lo tiles ----
        {
            const __nv_bfloat16* khb = g_qhl + (size_t)(kt * 64) * QKV_N + NH * HD + kh * HD;
            const __nv_bfloat16* vhb = khb + NKV * HD;
            load_tile(OKH, khb);
            load_tile(OKL, khb + LOFF);
            load_tile(OVH, vhb);
            load_tile(OVL, vhb + LOFF);
            cp_commit();
            cp_wait0();
        }
        __syncthreads();

        // ---- S = Q K^T (3 split passes) ----
        float sacc[4][4];
#pragma unroll
        for (int j = 0; j < 4; ++j)
#pragma unroll
            for (int e = 0; e < 4; ++e) sacc[j][e] = 0.f;

#pragma unroll 1
        for (int pass = 0; pass < 3; ++pass) {
            const uint32_t Ab = SB + ((pass == 1) ? OQL : OQH);
            const uint32_t Bb = SB + ((pass == 2) ? OKL : OKH);
#pragma unroll 4
            for (int ks = 0; ks < 16; ++ks) {
                uint32_t af[4];
                ldsm_x4(Ab + (wm * 16 + aRowOff) * ARS + ks * 32 + aColOff, af);
#pragma unroll
                for (int j = 0; j < 4; ++j) {
                    uint32_t bf[2];
                    ldsm_x2(Bb + (wn * 32 + j * 8 + bRow) * ARS + ks * 32 + bCol, bf);
                    mma16816(sacc[j], af[0], af[1], af[2], af[3], bf[0], bf[1]);
                }
            }
        }

        // ---- scale + softcap + causal mask, store S ----
#pragma unroll
        for (int j = 0; j < 4; ++j) {
            int colb = wn * 32 + j * 8 + (lane & 3) * 2;
            int kc0 = kt * 64 + colb;
#pragma unroll
            for (int hf = 0; hf < 2; ++hf) {
                int r = r0 + hf * 8;
                int qrow = qt * 64 + r;
                float x0 = 50.0f * tanhf(sacc[j][hf * 2] * SCALE * 0.02f);
                float x1 = 50.0f * tanhf(sacc[j][hf * 2 + 1] * SCALE * 0.02f);
                if (kc0 > qrow)     x0 = -1e30f;
                if (kc0 + 1 > qrow) x1 = -1e30f;
                *reinterpret_cast<float2*>(sm + OSP + r * SRS + colb * 4) =
                    make_float2(x0, x1);
            }
        }
        __syncthreads();

        // ---- softmax: 4 threads per row; keep p in regs across barrier ----
        const int row = tid >> 2;
        const int q4  = tid & 3;
        float p[16];
        {
            const float* srow = (const float*)(sm + OSP + row * SRS) + q4 * 16;
            float mold = m_s[row];
            float mt = mold;
#pragma unroll
            for (int c = 0; c < 16; ++c) mt = fmaxf(mt, srow[c]);
            mt = fmaxf(mt, __shfl_xor_sync(0xFFFFFFFFu, mt, 1));
            mt = fmaxf(mt, __shfl_xor_sync(0xFFFFFFFFu, mt, 2));
            float sum = 0.f;
#pragma unroll
            for (int c = 0; c < 16; ++c) {
                p[c] = __expf(srow[c] - mt);
                sum += p[c];
            }
            sum += __shfl_xor_sync(0xFFFFFFFFu, sum, 1);
            sum += __shfl_xor_sync(0xFFFFFFFFu, sum, 2);
            if (q4 == 0) {
                float alpha = __expf(mold - mt);
                l_s[row] = l_s[row] * alpha + sum;
                m_s[row] = mt;
                a_s[row] = alpha;
            }
        }
        __syncthreads();   // all S reads done; P overlay now safe

        // ---- write P hi/lo (overlays S region) ----
        {
            __nv_bfloat16* ph = (__nv_bfloat16*)(sm + OSP + row * PRS) + q4 * 16;
            __nv_bfloat16* pl = (__nv_bfloat16*)(sm + OPL + row * PRS) + q4 * 16;
#pragma unroll
            for (int c = 0; c < 16; ++c) {
                __nv_bfloat16 hp = __float2bfloat16(p[c]);
                ph[c] = hp;
                pl[c] = __float2bfloat16(p[c] - __bfloat162float(hp));
            }
        }
        // ---- rescale O accumulators by alpha ----
        {
            float al0 = a_s[r0], al1 = a_s[r0 + 8];
#pragma unroll
            for (int j = 0; j < 16; ++j) {
                oacc[j][0] *= al0; oacc[j][1] *= al0;
                oacc[j][2] *= al1; oacc[j][3] *= al1;
            }
        }
        __syncthreads();

        // ---- O += P V (3 split passes; B via ldmatrix.trans on V[t][d]) ----
#pragma unroll 1
        for (int pass = 0; pass < 3; ++pass) {
            const uint32_t Ab = SB + ((pass == 1) ? OPL : OSP);
            const uint32_t Bb = SB + ((pass == 2) ? OVL : OVH);
#pragma unroll
            for (int ks = 0; ks < 4; ++ks) {
                uint32_t af[4];
                ldsm_x4(Ab + (wm * 16 + aRowOff) * PRS + ks * 32 + aColOff, af);
#pragma unroll
                for (int j = 0; j < 16; ++j) {
                    uint32_t bf[2];
                    ldsm_x2t(Bb + (ks * 16 + lnb) * ARS + (wn * 128 + j * 8) * 2, bf);
                    mma16816(oacc[j], af[0], af[1], af[2], af[3], bf[0], bf[1]);
                }
            }
        }
    }

    // ---- epilogue: O /= l, split hi/lo, write O-proj A' panels directly ----
    {
        float il0 = 1.0f / l_s[r0];
        float il1 = 1.0f / l_s[r0 + 8];
        size_t row0 = (size_t)(qt * 64 + r0);
#pragma unroll
        for (int j = 0; j < 16; ++j) {
            int col = h * HD + wn * 128 + j * 8 + (lane & 3) * 2;
            uint32_t hi, lo;
            split2(oacc[j][0] * il0, oacc[j][1] * il0, hi, lo);
            __nv_bfloat16* a0 = g_Ao + row0 * K3O;
            *reinterpret_cast<uint32_t*>(a0 + col)               = hi;
            *reinterpret_cast<uint32_t*>(a0 + OPROJ_K + col)     = lo;
            *reinterpret_cast<uint32_t*>(a0 + 2 * OPROJ_K + col) = hi;
            split2(oacc[j][2] * il1, oacc[j][3] * il1, hi, lo);
            __nv_bfloat16* a1 = g_Ao + (row0 + 8) * K3O;
            *reinterpret_cast<uint32_t*>(a1 + col)               = hi;
            *reinterpret_cast<uint32_t*>(a1 + OPROJ_K + col)     = lo;
            *reinterpret_cast<uint32_t*>(a1 + 2 * OPROJ_K + col) = hi;
        }
    }
}

// ---------------- launch ----------------
extern "C" void kernel_launch(void* const* d_in, const int* in_sizes, int n_in,
                              void* d_out, int out_size) {
    const int*   positions = (const int*)d_in[0];
    const float* hidden    = (const float*)d_in[1];
    const float* w_qkv     = (const float*)d_in[2];
    const float* w_o       = (const float*)d_in[3];
    float*       out       = (float*)d_out;

    float* qkv_ptr = nullptr;
    __nv_bfloat16 *aq, *bq, *ao, *bo;
    cudaGetSymbolAddress((void**)&qkv_ptr, g_qkv);
    cudaGetSymbolAddress((void**)&aq, g_Aq);
    cudaGetSymbolAddress((void**)&bq, g_Bq);
    cudaGetSymbolAddress((void**)&ao, g_Ao);
    cudaGetSymbolAddress((void**)&bo, g_Bo);

    cudaFuncSetAttribute(attn_mma_kernel, cudaFuncAttributeMaxDynamicSharedMemorySize,
                         ATTN2_SMEM);

    // 1) split-convert inputs for QKV gemm
    conv_a_kernel<<<(TT * HID + 255) / 256, 256>>>(hidden, aq, TT, HID, K3Q);
    conv_bt_kernel<<<dim3(QKV_N / 32, HID / 32), dim3(32, 8)>>>(w_qkv, bq, HID, QKV_N, K3Q);

    // 2) QKV projection (HMMA)
    gemm_mma_kernel<<<dim3(QKV_N / HB_BN, TT / HB_BM), 256>>>(aq, bq, qkv_ptr, QKV_N, K3Q);

    // 3) fused RoPE + bf16 hi/lo split -> g_qhl
    {
        int total = TT * (NH + 2 * NKV) * (HD / 2);
        rope_split_kernel<<<(total + 255) / 256, 256>>>(positions);
    }

    // 4) causal GQA attention with soft-cap (HMMA flash) -> g_Ao (split panels)
    attn_mma_kernel<<<dim3(TT / 64, NH), 256, ATTN2_SMEM>>>();

    // 5) weight split for O-proj
    conv_bt_kernel<<<dim3(HID / 32, OPROJ_K / 32), dim3(32, 8)>>>(w_o, bo, OPROJ_K, HID, K3O);

    // 6) output projection (HMMA) -> out
    gemm_mma_kernel<<<dim3(HID / HB_BN, TT / HB_BM), 256>>>(ao, bo, out, HID, K3O);
}